// round 2
// baseline (speedup 1.0000x reference)
#include <cuda_runtime.h>
#include <cstdint>

#define B_SZ  512
#define NIN   1024
#define NMID  8192
#define NOUT  1000
#define FAN   64
#define NCOND 2

#define BM 128
#define BN 128
#define BK 16
#define SST 132           // smem row stride (pad: 132 % 32 = 4 -> 2-way store conflicts, 16B aligned)
#define KSPLIT 4
#define KCHUNK (NMID / KSPLIT)

// Scratch (static device globals per harness rules)
__device__ float4 g_act0v[(size_t)NMID * B_SZ / 4];          // 16 MB, transposed act [NMID][B]
__device__ float4 g_act1v[(size_t)NMID * B_SZ / 4];          // 16 MB
__device__ float2 g_pk[NCOND][(size_t)FAN * NMID];           // 8 MB: {w, idx} f-major

// ---------------------------------------------------------------------------
// prep: transpose W_mid / indx_seqs to f-major and pack {w, idx} into float2
// NOTE: indx_seqs is int32 on device (JAX x64 disabled downcasts int64->int32)
// ---------------------------------------------------------------------------
__global__ void prep_kernel(const int* __restrict__ idx,
                            const float* __restrict__ Wmid) {
    int t = blockIdx.x * blockDim.x + threadIdx.x;
    if (t >= FAN * NMID) return;
    int f = t / NMID, o = t - f * NMID;
    int j = idx[(size_t)o * FAN + f] & (NMID - 1);   // clamp defensively
    g_pk[0][t] = make_float2(Wmid[(size_t)o * FAN + f], __int_as_float(j));
    g_pk[1][t] = make_float2(Wmid[(size_t)NMID * FAN + (size_t)o * FAN + f], __int_as_float(j));
}

// ---------------------------------------------------------------------------
// shared 128x128x16 inner product (8x8 per thread)
// ---------------------------------------------------------------------------
__device__ __forceinline__ void mm_inner(const float* As, const float* Bs,
                                         int tx, int ty, float acc[8][8]) {
#pragma unroll
    for (int k = 0; k < BK; k++) {
        float4 a0 = *(const float4*)&As[k * SST + ty * 8];
        float4 a1 = *(const float4*)&As[k * SST + ty * 8 + 4];
        float4 b0 = *(const float4*)&Bs[k * SST + tx * 8];
        float4 b1 = *(const float4*)&Bs[k * SST + tx * 8 + 4];
        float a[8] = {a0.x, a0.y, a0.z, a0.w, a1.x, a1.y, a1.z, a1.w};
        float b[8] = {b0.x, b0.y, b0.z, b0.w, b1.x, b1.y, b1.z, b1.w};
#pragma unroll
        for (int i = 0; i < 8; i++)
#pragma unroll
            for (int j = 0; j < 8; j++)
                acc[i][j] = fmaf(a[i], b[j], acc[i][j]);
    }
}

// ---------------------------------------------------------------------------
// GEMM1: g_act0[m][n] = relu( sum_k W_in[m][k] * x[n][k] + b_in[m] )
// A = W_in [NMID, NIN], B = x [B_SZ, NIN]   (both K-contiguous)
// ---------------------------------------------------------------------------
__global__ __launch_bounds__(256) void gemm1_kernel(const float* __restrict__ A,
                                                    const float* __restrict__ Bm,
                                                    const float* __restrict__ bias) {
    __shared__ float As[BK * SST];
    __shared__ float Bs[BK * SST];
    int tid = threadIdx.x;
    int m0 = blockIdx.y * BM, n0 = blockIdx.x * BN;
    int tx = tid & 15, ty = tid >> 4;
    int rr = tid >> 2;
    int kq = (tid & 3) * 4;
    float acc[8][8] = {};

    for (int k0 = 0; k0 < NIN; k0 += BK) {
#pragma unroll
        for (int p = 0; p < 2; p++) {
            int r = rr + p * 64;
            float4 va = *(const float4*)&A[(size_t)(m0 + r) * NIN + k0 + kq];
            float4 vb = *(const float4*)&Bm[(size_t)(n0 + r) * NIN + k0 + kq];
            As[(kq + 0) * SST + r] = va.x; As[(kq + 1) * SST + r] = va.y;
            As[(kq + 2) * SST + r] = va.z; As[(kq + 3) * SST + r] = va.w;
            Bs[(kq + 0) * SST + r] = vb.x; Bs[(kq + 1) * SST + r] = vb.y;
            Bs[(kq + 2) * SST + r] = vb.z; Bs[(kq + 3) * SST + r] = vb.w;
        }
        __syncthreads();
        mm_inner(As, Bs, tx, ty, acc);
        __syncthreads();
    }

    float* C = (float*)g_act0v;
#pragma unroll
    for (int i = 0; i < 8; i++) {
        int m = m0 + ty * 8 + i;
        float bv = bias[m];
        float4 o0, o1;
        o0.x = fmaxf(acc[i][0] + bv, 0.f); o0.y = fmaxf(acc[i][1] + bv, 0.f);
        o0.z = fmaxf(acc[i][2] + bv, 0.f); o0.w = fmaxf(acc[i][3] + bv, 0.f);
        o1.x = fmaxf(acc[i][4] + bv, 0.f); o1.y = fmaxf(acc[i][5] + bv, 0.f);
        o1.z = fmaxf(acc[i][6] + bv, 0.f); o1.w = fmaxf(acc[i][7] + bv, 0.f);
        *(float4*)&C[(size_t)m * B_SZ + n0 + tx * 8]     = o0;
        *(float4*)&C[(size_t)m * B_SZ + n0 + tx * 8 + 4] = o1;
    }
}

// ---------------------------------------------------------------------------
// Condensed layer: hout[o][b] = relu( sum_f w[o,f] * hin[idx[o,f]][b] + bias[o] )
// One CTA per 4-wide batch slice; slice staged in 128 KB dynamic smem.
// ---------------------------------------------------------------------------
__global__ __launch_bounds__(256) void cond_kernel(int phase, const float* __restrict__ bias) {
    extern __shared__ float4 hs[];   // [NMID]
    const float* hin  = (phase == 0) ? (const float*)g_act0v : (const float*)g_act1v;
    float*       hout = (phase == 0) ? (float*)g_act1v       : (float*)g_act0v;
    const float2* pk = g_pk[phase];
    int b0 = blockIdx.x * 4;

    for (int j = threadIdx.x; j < NMID; j += blockDim.x)
        hs[j] = *(const float4*)&hin[(size_t)j * B_SZ + b0];
    __syncthreads();

    for (int o = threadIdx.x; o < NMID; o += blockDim.x) {
        float ax = 0.f, ay = 0.f, az = 0.f, aw = 0.f;
#pragma unroll 8
        for (int f = 0; f < FAN; f++) {
            float2 p = pk[(size_t)f * NMID + o];
            float4 h = hs[__float_as_int(p.y)];
            ax = fmaf(p.x, h.x, ax);
            ay = fmaf(p.x, h.y, ay);
            az = fmaf(p.x, h.z, az);
            aw = fmaf(p.x, h.w, aw);
        }
        float bv = bias[o];
        float4 r;
        r.x = fmaxf(ax + bv, 0.f); r.y = fmaxf(ay + bv, 0.f);
        r.z = fmaxf(az + bv, 0.f); r.w = fmaxf(aw + bv, 0.f);
        *(float4*)&hout[(size_t)o * B_SZ + b0] = r;
    }
}

// ---------------------------------------------------------------------------
// init output with bias (gemm3 accumulates atomically on top)
// ---------------------------------------------------------------------------
__global__ void init_out_kernel(const float* __restrict__ bout, float* __restrict__ out) {
    int t = blockIdx.x * blockDim.x + threadIdx.x;
    if (t < B_SZ * NOUT) out[t] = bout[t % NOUT];
}

// ---------------------------------------------------------------------------
// GEMM3 (split-K): out[n][m] += sum_k W_out[m][k] * act[k][n]
// A = W_out [NOUT, NMID] K-contiguous; B = g_act0 [NMID, B_SZ] k-major (no transpose needed)
// ---------------------------------------------------------------------------
__global__ __launch_bounds__(256) void gemm3_kernel(const float* __restrict__ A,
                                                    float* __restrict__ out) {
    const float* Bm = (const float*)g_act0v;
    __shared__ float As[BK * SST];
    __shared__ float Bs[BK * SST];
    int tid = threadIdx.x;
    int m0 = blockIdx.y * BM, n0 = blockIdx.x * BN;
    int kbase = blockIdx.z * KCHUNK;
    int tx = tid & 15, ty = tid >> 4;
    int rr = tid >> 2;
    int kq = (tid & 3) * 4;
    int kb = tid >> 5;            // 0..7
    int nq = (tid & 31) * 4;      // 0..124
    float acc[8][8] = {};

    for (int kt = 0; kt < KCHUNK; kt += BK) {
        int k0 = kbase + kt;
#pragma unroll
        for (int p = 0; p < 2; p++) {
            int r = rr + p * 64;
            float4 va = (m0 + r < NOUT)
                ? *(const float4*)&A[(size_t)(m0 + r) * NMID + k0 + kq]
                : make_float4(0.f, 0.f, 0.f, 0.f);
            As[(kq + 0) * SST + r] = va.x; As[(kq + 1) * SST + r] = va.y;
            As[(kq + 2) * SST + r] = va.z; As[(kq + 3) * SST + r] = va.w;
            int k = kb + p * 8;
            *(float4*)&Bs[k * SST + nq] =
                *(const float4*)&Bm[(size_t)(k0 + k) * B_SZ + n0 + nq];
        }
        __syncthreads();
        mm_inner(As, Bs, tx, ty, acc);
        __syncthreads();
    }

#pragma unroll
    for (int i = 0; i < 8; i++) {
        int m = m0 + ty * 8 + i;
        if (m >= NOUT) continue;
#pragma unroll
        for (int j = 0; j < 8; j++)
            atomicAdd(&out[(size_t)(n0 + tx * 8 + j) * NOUT + m], acc[i][j]);
    }
}

// ---------------------------------------------------------------------------
extern "C" void kernel_launch(void* const* d_in, const int* in_sizes, int n_in,
                              void* d_out, int out_size) {
    const float* x    = (const float*)d_in[0];
    const float* Win  = (const float*)d_in[1];
    const float* bin  = (const float*)d_in[2];
    const float* Wmid = (const float*)d_in[3];
    const float* bmid = (const float*)d_in[4];
    const float* Wout = (const float*)d_in[5];
    const float* bout = (const float*)d_in[6];
    const int*   idx  = (const int*)d_in[7];    // int32 (JAX x64 disabled)
    float* out = (float*)d_out;

    cudaFuncSetAttribute(cond_kernel,
                         cudaFuncAttributeMaxDynamicSharedMemorySize, 131072);

    prep_kernel<<<(FAN * NMID) / 256, 256>>>(idx, Wmid);
    gemm1_kernel<<<dim3(B_SZ / BN, NMID / BM), 256>>>(Win, x, bin);
    cond_kernel<<<B_SZ / 4, 256, 131072>>>(0, bmid);
    cond_kernel<<<B_SZ / 4, 256, 131072>>>(1, bmid + NMID);
    init_out_kernel<<<(B_SZ * NOUT + 255) / 256, 256>>>(bout, out);
    gemm3_kernel<<<dim3(B_SZ / BN, (NOUT + BM - 1) / BM, KSPLIT), 256>>>(Wout, out);
}

// round 3
// speedup vs baseline: 1.1087x; 1.1087x over previous
#include <cuda_runtime.h>
#include <cstdint>

#define B_SZ  512
#define NIN   1024
#define NMID  8192
#define NOUT  1000
#define FAN   64
#define NCOND 2

#define BM 128
#define BN 128
#define BK 16
#define SST 132
#define KSPLIT 4
#define KCHUNK (NMID / KSPLIT)

// Scratch (static device globals per harness rules)
__device__ float4 g_act0v[(size_t)NMID * B_SZ / 4];             // 16 MB, transposed act [NMID][B]
__device__ float4 g_act1v[(size_t)NMID * B_SZ / 4];             // 16 MB
__device__ float4 g_wf4[NCOND][(size_t)(FAN / 4) * NMID];       // 4 MB: w, 4 f per load, o-contig
__device__ uint4  g_if4[(size_t)(FAN / 8) * NMID];              // 1 MB: idx u16, 8 f per load

// ---------------------------------------------------------------------------
// prep: pack W_mid into float4 groups (f-major, o-contiguous) and indx_seqs
// into u16 x8 uint4 groups. indx_seqs is int32 on device (JAX x64 disabled).
// ---------------------------------------------------------------------------
__global__ void prep_w_kernel(const float* __restrict__ Wmid) {
    int t = blockIdx.x * blockDim.x + threadIdx.x;       // NCOND * 16 * NMID
    if (t >= NCOND * (FAN / 4) * NMID) return;
    int phase = t / ((FAN / 4) * NMID);
    int rem = t - phase * (FAN / 4) * NMID;
    int g = rem / NMID, o = rem - g * NMID;
    const float* src = Wmid + (size_t)(phase * NMID + o) * FAN + g * 4;
    g_wf4[phase][(size_t)g * NMID + o] = make_float4(src[0], src[1], src[2], src[3]);
}

__global__ void prep_i_kernel(const int* __restrict__ idx) {
    int t = blockIdx.x * blockDim.x + threadIdx.x;       // 8 * NMID
    if (t >= (FAN / 8) * NMID) return;
    int g = t / NMID, o = t - g * NMID;
    const int* src = idx + (size_t)o * FAN + g * 8;
    uint4 v;
    v.x = (unsigned)(src[0] & (NMID - 1)) | ((unsigned)(src[1] & (NMID - 1)) << 16);
    v.y = (unsigned)(src[2] & (NMID - 1)) | ((unsigned)(src[3] & (NMID - 1)) << 16);
    v.z = (unsigned)(src[4] & (NMID - 1)) | ((unsigned)(src[5] & (NMID - 1)) << 16);
    v.w = (unsigned)(src[6] & (NMID - 1)) | ((unsigned)(src[7] & (NMID - 1)) << 16);
    g_if4[(size_t)g * NMID + o] = v;
}

// ---------------------------------------------------------------------------
// shared 128x128x16 inner product (8x8 per thread)
// ---------------------------------------------------------------------------
__device__ __forceinline__ void mm_inner(const float* As, const float* Bs,
                                         int tx, int ty, float acc[8][8]) {
#pragma unroll
    for (int k = 0; k < BK; k++) {
        float4 a0 = *(const float4*)&As[k * SST + ty * 8];
        float4 a1 = *(const float4*)&As[k * SST + ty * 8 + 4];
        float4 b0 = *(const float4*)&Bs[k * SST + tx * 8];
        float4 b1 = *(const float4*)&Bs[k * SST + tx * 8 + 4];
        float a[8] = {a0.x, a0.y, a0.z, a0.w, a1.x, a1.y, a1.z, a1.w};
        float b[8] = {b0.x, b0.y, b0.z, b0.w, b1.x, b1.y, b1.z, b1.w};
#pragma unroll
        for (int i = 0; i < 8; i++)
#pragma unroll
            for (int j = 0; j < 8; j++)
                acc[i][j] = fmaf(a[i], b[j], acc[i][j]);
    }
}

// ---------------------------------------------------------------------------
// GEMM1: g_act0[m][n] = relu( sum_k W_in[m][k] * x[n][k] + b_in[m] )
// ---------------------------------------------------------------------------
__global__ __launch_bounds__(256) void gemm1_kernel(const float* __restrict__ A,
                                                    const float* __restrict__ Bm,
                                                    const float* __restrict__ bias) {
    __shared__ float As[BK * SST];
    __shared__ float Bs[BK * SST];
    int tid = threadIdx.x;
    int m0 = blockIdx.y * BM, n0 = blockIdx.x * BN;
    int tx = tid & 15, ty = tid >> 4;
    int rr = tid >> 2;
    int kq = (tid & 3) * 4;
    float acc[8][8] = {};

    for (int k0 = 0; k0 < NIN; k0 += BK) {
#pragma unroll
        for (int p = 0; p < 2; p++) {
            int r = rr + p * 64;
            float4 va = *(const float4*)&A[(size_t)(m0 + r) * NIN + k0 + kq];
            float4 vb = *(const float4*)&Bm[(size_t)(n0 + r) * NIN + k0 + kq];
            As[(kq + 0) * SST + r] = va.x; As[(kq + 1) * SST + r] = va.y;
            As[(kq + 2) * SST + r] = va.z; As[(kq + 3) * SST + r] = va.w;
            Bs[(kq + 0) * SST + r] = vb.x; Bs[(kq + 1) * SST + r] = vb.y;
            Bs[(kq + 2) * SST + r] = vb.z; Bs[(kq + 3) * SST + r] = vb.w;
        }
        __syncthreads();
        mm_inner(As, Bs, tx, ty, acc);
        __syncthreads();
    }

    float* C = (float*)g_act0v;
#pragma unroll
    for (int i = 0; i < 8; i++) {
        int m = m0 + ty * 8 + i;
        float bv = bias[m];
        float4 o0, o1;
        o0.x = fmaxf(acc[i][0] + bv, 0.f); o0.y = fmaxf(acc[i][1] + bv, 0.f);
        o0.z = fmaxf(acc[i][2] + bv, 0.f); o0.w = fmaxf(acc[i][3] + bv, 0.f);
        o1.x = fmaxf(acc[i][4] + bv, 0.f); o1.y = fmaxf(acc[i][5] + bv, 0.f);
        o1.z = fmaxf(acc[i][6] + bv, 0.f); o1.w = fmaxf(acc[i][7] + bv, 0.f);
        *(float4*)&C[(size_t)m * B_SZ + n0 + tx * 8]     = o0;
        *(float4*)&C[(size_t)m * B_SZ + n0 + tx * 8 + 4] = o1;
    }
}

// ---------------------------------------------------------------------------
// Condensed layer: hout[o][b] = relu( sum_f w[o,f] * hin[idx[o,f]][b] + bias[o] )
// One CTA per 4-wide batch slice staged in 128 KB smem; 1024 threads (32 warps)
// for latency hiding; packed u16 idx + float4 w to cut LDG count 64 -> 24 per o.
// ---------------------------------------------------------------------------
__global__ __launch_bounds__(1024) void cond_kernel(int phase, const float* __restrict__ bias) {
    extern __shared__ float4 hs[];   // [NMID]
    const float4* hin  = (phase == 0) ? g_act0v : g_act1v;
    float4*       hout = (phase == 0) ? g_act1v : g_act0v;
    const float4* wp = g_wf4[phase];
    int bq = blockIdx.x;             // float4 column index (b0 = 4*bq)
    int tid = threadIdx.x;

    for (int j = tid; j < NMID; j += 1024)
        hs[j] = hin[(size_t)j * (B_SZ / 4) + bq];
    __syncthreads();

#pragma unroll
    for (int oi = 0; oi < NMID / 1024; oi++) {
        int o = oi * 1024 + tid;
        float ax = 0.f, ay = 0.f, az = 0.f, aw = 0.f;
#pragma unroll
        for (int g = 0; g < FAN / 8; g++) {
            uint4 iv = g_if4[(size_t)g * NMID + o];
            float4 w0 = wp[(size_t)(2 * g) * NMID + o];
            float4 w1 = wp[(size_t)(2 * g + 1) * NMID + o];
            float4 h0 = hs[iv.x & 0xffff];
            float4 h1 = hs[iv.x >> 16];
            float4 h2 = hs[iv.y & 0xffff];
            float4 h3 = hs[iv.y >> 16];
            float4 h4 = hs[iv.z & 0xffff];
            float4 h5 = hs[iv.z >> 16];
            float4 h6 = hs[iv.w & 0xffff];
            float4 h7 = hs[iv.w >> 16];
            ax = fmaf(w0.x, h0.x, ax); ay = fmaf(w0.x, h0.y, ay);
            az = fmaf(w0.x, h0.z, az); aw = fmaf(w0.x, h0.w, aw);
            ax = fmaf(w0.y, h1.x, ax); ay = fmaf(w0.y, h1.y, ay);
            az = fmaf(w0.y, h1.z, az); aw = fmaf(w0.y, h1.w, aw);
            ax = fmaf(w0.z, h2.x, ax); ay = fmaf(w0.z, h2.y, ay);
            az = fmaf(w0.z, h2.z, az); aw = fmaf(w0.z, h2.w, aw);
            ax = fmaf(w0.w, h3.x, ax); ay = fmaf(w0.w, h3.y, ay);
            az = fmaf(w0.w, h3.z, az); aw = fmaf(w0.w, h3.w, aw);
            ax = fmaf(w1.x, h4.x, ax); ay = fmaf(w1.x, h4.y, ay);
            az = fmaf(w1.x, h4.z, az); aw = fmaf(w1.x, h4.w, aw);
            ax = fmaf(w1.y, h5.x, ax); ay = fmaf(w1.y, h5.y, ay);
            az = fmaf(w1.y, h5.z, az); aw = fmaf(w1.y, h5.w, aw);
            ax = fmaf(w1.z, h6.x, ax); ay = fmaf(w1.z, h6.y, ay);
            az = fmaf(w1.z, h6.z, az); aw = fmaf(w1.z, h6.w, aw);
            ax = fmaf(w1.w, h7.x, ax); ay = fmaf(w1.w, h7.y, ay);
            az = fmaf(w1.w, h7.z, az); aw = fmaf(w1.w, h7.w, aw);
        }
        float bv = bias[o];
        float4 r;
        r.x = fmaxf(ax + bv, 0.f); r.y = fmaxf(ay + bv, 0.f);
        r.z = fmaxf(az + bv, 0.f); r.w = fmaxf(aw + bv, 0.f);
        hout[(size_t)o * (B_SZ / 4) + bq] = r;
    }
}

// ---------------------------------------------------------------------------
__global__ void init_out_kernel(const float* __restrict__ bout, float* __restrict__ out) {
    int t = blockIdx.x * blockDim.x + threadIdx.x;
    if (t < B_SZ * NOUT) out[t] = bout[t % NOUT];
}

// ---------------------------------------------------------------------------
// GEMM3 (split-K): out[n][m] += sum_k W_out[m][k] * act[k][n]
// ---------------------------------------------------------------------------
__global__ __launch_bounds__(256) void gemm3_kernel(const float* __restrict__ A,
                                                    float* __restrict__ out) {
    const float* Bm = (const float*)g_act0v;
    __shared__ float As[BK * SST];
    __shared__ float Bs[BK * SST];
    int tid = threadIdx.x;
    int m0 = blockIdx.y * BM, n0 = blockIdx.x * BN;
    int kbase = blockIdx.z * KCHUNK;
    int tx = tid & 15, ty = tid >> 4;
    int rr = tid >> 2;
    int kq = (tid & 3) * 4;
    int kb = tid >> 5;
    int nq = (tid & 31) * 4;
    float acc[8][8] = {};

    for (int kt = 0; kt < KCHUNK; kt += BK) {
        int k0 = kbase + kt;
#pragma unroll
        for (int p = 0; p < 2; p++) {
            int r = rr + p * 64;
            float4 va = (m0 + r < NOUT)
                ? *(const float4*)&A[(size_t)(m0 + r) * NMID + k0 + kq]
                : make_float4(0.f, 0.f, 0.f, 0.f);
            As[(kq + 0) * SST + r] = va.x; As[(kq + 1) * SST + r] = va.y;
            As[(kq + 2) * SST + r] = va.z; As[(kq + 3) * SST + r] = va.w;
            int k = kb + p * 8;
            *(float4*)&Bs[k * SST + nq] =
                *(const float4*)&Bm[(size_t)(k0 + k) * B_SZ + n0 + nq];
        }
        __syncthreads();
        mm_inner(As, Bs, tx, ty, acc);
        __syncthreads();
    }

#pragma unroll
    for (int i = 0; i < 8; i++) {
        int m = m0 + ty * 8 + i;
        if (m >= NOUT) continue;
#pragma unroll
        for (int j = 0; j < 8; j++)
            atomicAdd(&out[(size_t)(n0 + tx * 8 + j) * NOUT + m], acc[i][j]);
    }
}

// ---------------------------------------------------------------------------
extern "C" void kernel_launch(void* const* d_in, const int* in_sizes, int n_in,
                              void* d_out, int out_size) {
    const float* x    = (const float*)d_in[0];
    const float* Win  = (const float*)d_in[1];
    const float* bin  = (const float*)d_in[2];
    const float* Wmid = (const float*)d_in[3];
    const float* bmid = (const float*)d_in[4];
    const float* Wout = (const float*)d_in[5];
    const float* bout = (const float*)d_in[6];
    const int*   idx  = (const int*)d_in[7];    // int32 (JAX x64 disabled)
    float* out = (float*)d_out;

    cudaFuncSetAttribute(cond_kernel,
                         cudaFuncAttributeMaxDynamicSharedMemorySize, 131072);

    prep_w_kernel<<<(NCOND * (FAN / 4) * NMID + 255) / 256, 256>>>(Wmid);
    prep_i_kernel<<<((FAN / 8) * NMID + 255) / 256, 256>>>(idx);
    gemm1_kernel<<<dim3(B_SZ / BN, NMID / BM), 256>>>(Win, x, bin);
    cond_kernel<<<B_SZ / 4, 1024, 131072>>>(0, bmid);
    cond_kernel<<<B_SZ / 4, 1024, 131072>>>(1, bmid + NMID);
    init_out_kernel<<<(B_SZ * NOUT + 255) / 256, 256>>>(bout, out);
    gemm3_kernel<<<dim3(B_SZ / BN, (NOUT + BM - 1) / BM, KSPLIT), 256>>>(Wout, out);
}

// round 7
// speedup vs baseline: 1.6961x; 1.5298x over previous
#include <cuda_runtime.h>
#include <cuda_bf16.h>
#include <cstdint>

#define B_SZ  512
#define NIN   1024
#define NMID  8192
#define NOUT  1000
#define MPAD  1024
#define FAN   64
#define NCOND 2

#define K1 (3 * NIN)      // 3072  concat K for GEMM1
#define K3 (3 * NMID)     // 24576 concat K for GEMM3

// warp-MMA GEMM tiling
#define TBM 128
#define TBN 128
#define TBK 32
#define ROWB 80           // smem row stride bytes (64B data + 16B pad; 20 words -> conflict-free)
#define GEMM_THREADS 256

// ---------------------------------------------------------------------------
// Scratch (static device globals; referenced ONLY inside device code --
// passing them as kernel args from host binds the host shadow, which on
// GB300/ATS silently reads zeros / writes host RAM: the R5/R6 bug)
// ---------------------------------------------------------------------------
__device__ float4 g_act0v[(size_t)NMID * B_SZ / 4];           // fp32 [o][b]
__device__ float4 g_act1v[(size_t)NMID * B_SZ / 4];           // fp32 [o][b]
__device__ float4 g_wf4[NCOND][(size_t)(FAN / 4) * NMID];     // cond w packed
__device__ uint4  g_if4[(size_t)(FAN / 8) * NMID];            // cond idx packed u16
__device__ __nv_bfloat16 g_wi3[(size_t)NMID * K1];            // [Wh|Wl|Wh]
__device__ __nv_bfloat16 g_x3[(size_t)B_SZ * K1];             // [xh|xh|xl]
__device__ __nv_bfloat16 g_wo3[(size_t)MPAD * K3];            // [Wh|Wl|Wh]
__device__ __nv_bfloat16 g_a13[(size_t)B_SZ * K3];            // [ah|ah|al]

// ---------------------------------------------------------------------------
__device__ __forceinline__ void mma16816(float* d,
                                         uint32_t a0, uint32_t a1, uint32_t a2, uint32_t a3,
                                         uint32_t b0, uint32_t b1) {
    asm volatile(
        "mma.sync.aligned.m16n8k16.row.col.f32.bf16.bf16.f32 "
        "{%0,%1,%2,%3}, {%4,%5,%6,%7}, {%8,%9}, {%0,%1,%2,%3};"
        : "+f"(d[0]), "+f"(d[1]), "+f"(d[2]), "+f"(d[3])
        : "r"(a0), "r"(a1), "r"(a2), "r"(a3), "r"(b0), "r"(b1));
}

// ---------------------------------------------------------------------------
// fp32 -> bf16 hi/lo split + K-concat conversion
// WHICH 0: Win  -> g_wi3, pattern [hi|lo|hi], K=NIN
// WHICH 1: x    -> g_x3,  pattern [hi|hi|lo], K=NIN
// WHICH 2: Wout -> g_wo3, pattern [hi|lo|hi], K=NMID, rows padded NOUT->MPAD
// ---------------------------------------------------------------------------
__device__ __forceinline__ void split_bf16(float v, __nv_bfloat16& h, __nv_bfloat16& l) {
    h = __float2bfloat16(v);
    l = __float2bfloat16(v - __bfloat162float(h));
}
template <int WHICH>
__global__ void cvt3_kernel(const float* __restrict__ src) {
    constexpr int K        = (WHICH == 2) ? NMID : NIN;
    constexpr int rowsTot  = (WHICH == 0) ? NMID : (WHICH == 1) ? B_SZ : MPAD;
    constexpr int rowsVal  = (WHICH == 2) ? NOUT : rowsTot;
    __nv_bfloat16* dst = (WHICH == 0) ? g_wi3 : (WHICH == 1) ? g_x3 : g_wo3;

    long long t = blockIdx.x * (long long)blockDim.x + threadIdx.x;
    if (t * 4 >= (long long)rowsTot * K) return;
    int row = (int)((t * 4) / K);
    int col = (int)((t * 4) % K);
    float4 v = (row < rowsVal)
        ? *(const float4*)(src + (size_t)row * K + col)
        : make_float4(0.f, 0.f, 0.f, 0.f);
    __nv_bfloat16 h0, h1, h2, h3, l0, l1, l2, l3;
    split_bf16(v.x, h0, l0); split_bf16(v.y, h1, l1);
    split_bf16(v.z, h2, l2); split_bf16(v.w, h3, l3);
    ushort4 hv = make_ushort4(__bfloat16_as_ushort(h0), __bfloat16_as_ushort(h1),
                              __bfloat16_as_ushort(h2), __bfloat16_as_ushort(h3));
    ushort4 lv = make_ushort4(__bfloat16_as_ushort(l0), __bfloat16_as_ushort(l1),
                              __bfloat16_as_ushort(l2), __bfloat16_as_ushort(l3));
    __nv_bfloat16* base = dst + (size_t)row * (3 * (size_t)K) + col;
    *(ushort4*)(base)         = hv;
    *(ushort4*)(base + K)     = (WHICH == 1) ? hv : lv;   // A-side: lo, B-side: hi
    *(ushort4*)(base + 2 * K) = (WHICH == 1) ? lv : hv;   // A-side: hi, B-side: lo
}

// ---------------------------------------------------------------------------
// cond prep
// ---------------------------------------------------------------------------
__global__ void prep_w_kernel(const float* __restrict__ Wmid) {
    int t = blockIdx.x * blockDim.x + threadIdx.x;
    if (t >= NCOND * (FAN / 4) * NMID) return;
    int phase = t / ((FAN / 4) * NMID);
    int rem = t - phase * (FAN / 4) * NMID;
    int g = rem / NMID, o = rem - g * NMID;
    const float* src = Wmid + (size_t)(phase * NMID + o) * FAN + g * 4;
    g_wf4[phase][(size_t)g * NMID + o] = make_float4(src[0], src[1], src[2], src[3]);
}
__global__ void prep_i_kernel(const int* __restrict__ idx) {
    int t = blockIdx.x * blockDim.x + threadIdx.x;
    if (t >= (FAN / 8) * NMID) return;
    int g = t / NMID, o = t - g * NMID;
    const int* src = idx + (size_t)o * FAN + g * 8;
    uint4 v;
    v.x = (unsigned)(src[0] & (NMID - 1)) | ((unsigned)(src[1] & (NMID - 1)) << 16);
    v.y = (unsigned)(src[2] & (NMID - 1)) | ((unsigned)(src[3] & (NMID - 1)) << 16);
    v.z = (unsigned)(src[4] & (NMID - 1)) | ((unsigned)(src[5] & (NMID - 1)) << 16);
    v.w = (unsigned)(src[6] & (NMID - 1)) | ((unsigned)(src[7] & (NMID - 1)) << 16);
    g_if4[(size_t)g * NMID + o] = v;
}

// ---------------------------------------------------------------------------
// warp-MMA bf16 GEMM: D[m][n] = sum_k A[m][k] * B[n][k]
// MODE 0: A=g_wi3 B=g_x3  Ks=K1, out: g_act0[m*B_SZ+n] = relu(D + bias[m])
// MODE 1: A=g_wo3 B=g_a13 Ks=K3, out: atomicAdd(out[n*NOUT+m], D) (split-K)
// ---------------------------------------------------------------------------
template <int MODE>
__global__ __launch_bounds__(GEMM_THREADS) void mma_gemm(
    const float* __restrict__ bias, float* __restrict__ outp, int kIters)
{
    const __nv_bfloat16* __restrict__ A = (MODE == 0) ? g_wi3 : g_wo3;
    const __nv_bfloat16* __restrict__ B = (MODE == 0) ? g_x3 : g_a13;
    float* out = (MODE == 0) ? (float*)g_act0v : outp;
    const int Ks = (MODE == 0) ? K1 : K3;

    __shared__ __align__(16) char smA[TBM * ROWB];
    __shared__ __align__(16) char smB[TBN * ROWB];

    int tid = threadIdx.x;
    int wid = tid >> 5, lid = tid & 31;
    int g = lid >> 2, t = lid & 3;
    int wm = (wid >> 1) * 32;               // warp M offset in tile
    int wn = (wid & 1) * 64;                // warp N offset in tile
    int m0 = blockIdx.y * TBM;
    int n0 = blockIdx.x * TBN;
    int kk0 = blockIdx.z * kIters * TBK;

    // staging: 512 16B-chunks per operand; thread handles chunks tid, tid+256
    int r0 = tid >> 2,          s0 = (tid & 3) * 16;           // bytes
    int r1 = (tid + 256) >> 2,  s1 = ((tid + 256) & 3) * 16;

    uint4 rA0, rA1, rB0, rB1;
    float acc[2][8][4] = {};

#define LDG_CHUNKS(it)                                                          \
    do {                                                                        \
        int kk = kk0 + (it) * TBK;                                              \
        rA0 = *(const uint4*)(A + (size_t)(m0 + r0) * Ks + kk + (s0 >> 1));     \
        rA1 = *(const uint4*)(A + (size_t)(m0 + r1) * Ks + kk + (s1 >> 1));     \
        rB0 = *(const uint4*)(B + (size_t)(n0 + r0) * Ks + kk + (s0 >> 1));     \
        rB1 = *(const uint4*)(B + (size_t)(n0 + r1) * Ks + kk + (s1 >> 1));     \
    } while (0)

    LDG_CHUNKS(0);

    for (int it = 0; it < kIters; it++) {
        __syncthreads();                    // previous compute done everywhere
        *(uint4*)(smA + r0 * ROWB + s0) = rA0;
        *(uint4*)(smA + r1 * ROWB + s1) = rA1;
        *(uint4*)(smB + r0 * ROWB + s0) = rB0;
        *(uint4*)(smB + r1 * ROWB + s1) = rB1;
        __syncthreads();
        if (it + 1 < kIters) LDG_CHUNKS(it + 1);   // hidden under compute below

#pragma unroll
        for (int ks = 0; ks < 2; ks++) {
            int koff = (ks * 16 + 2 * t) * 2;      // byte offset in row
            uint32_t a[2][4];
#pragma unroll
            for (int mi = 0; mi < 2; mi++) {
                const char* base = smA + (wm + mi * 16 + g) * ROWB + koff;
                a[mi][0] = *(const uint32_t*)(base);
                a[mi][1] = *(const uint32_t*)(base + 8 * ROWB);
                a[mi][2] = *(const uint32_t*)(base + 16);
                a[mi][3] = *(const uint32_t*)(base + 8 * ROWB + 16);
            }
#pragma unroll
            for (int nj = 0; nj < 4; nj++) {
                const char* bb = smB + (wn + nj * 16 + g) * ROWB + koff;
                uint32_t b0 = *(const uint32_t*)(bb);
                uint32_t b1 = *(const uint32_t*)(bb + 16);
                uint32_t b2 = *(const uint32_t*)(bb + 8 * ROWB);
                uint32_t b3 = *(const uint32_t*)(bb + 8 * ROWB + 16);
#pragma unroll
                for (int mi = 0; mi < 2; mi++) {
                    mma16816(acc[mi][nj * 2],     a[mi][0], a[mi][1], a[mi][2], a[mi][3], b0, b1);
                    mma16816(acc[mi][nj * 2 + 1], a[mi][0], a[mi][1], a[mi][2], a[mi][3], b2, b3);
                }
            }
        }
    }
#undef LDG_CHUNKS

    // epilogue: c0,c1 at (m, n=2t), c2,c3 at (m+8, n=2t)
    int mrow = g;
    int ncol = t * 2;
#pragma unroll
    for (int mi = 0; mi < 2; mi++) {
        int m = m0 + wm + mi * 16 + mrow;
        if (MODE == 0) {
            float bv0 = bias[m], bv8 = bias[m + 8];
#pragma unroll
            for (int n8 = 0; n8 < 8; n8++) {
                int n = n0 + wn + n8 * 8 + ncol;
                float* c = acc[mi][n8];
                float2 lo = make_float2(fmaxf(c[0] + bv0, 0.f), fmaxf(c[1] + bv0, 0.f));
                float2 hi = make_float2(fmaxf(c[2] + bv8, 0.f), fmaxf(c[3] + bv8, 0.f));
                *(float2*)(out + (size_t)m * B_SZ + n) = lo;
                *(float2*)(out + (size_t)(m + 8) * B_SZ + n) = hi;
            }
        } else {
#pragma unroll
            for (int n8 = 0; n8 < 8; n8++) {
                int n = n0 + wn + n8 * 8 + ncol;
                float* c = acc[mi][n8];
                if (m < NOUT) {
                    atomicAdd(out + (size_t)n * NOUT + m, c[0]);
                    atomicAdd(out + (size_t)(n + 1) * NOUT + m, c[1]);
                }
                if (m + 8 < NOUT) {
                    atomicAdd(out + (size_t)n * NOUT + m + 8, c[2]);
                    atomicAdd(out + (size_t)(n + 1) * NOUT + m + 8, c[3]);
                }
            }
        }
    }
}

// ---------------------------------------------------------------------------
// Condensed layer. phase 0: fp32 [o][b] -> fp32 [o][b]
//                  phase 1: fp32 [o][b] -> bf16 concat [b][3*NMID] (hi|hi|lo)
// ---------------------------------------------------------------------------
__global__ __launch_bounds__(1024) void cond_kernel(int phase, const float* __restrict__ bias) {
    extern __shared__ float4 hs[];   // [NMID]
    const float4* hin = (phase == 0) ? g_act0v : g_act1v;
    const float4* wp = g_wf4[phase];
    int bq = blockIdx.x;
    int b0 = bq * 4;
    int tid = threadIdx.x;

    for (int j = tid; j < NMID; j += 1024)
        hs[j] = hin[(size_t)j * (B_SZ / 4) + bq];
    __syncthreads();

#pragma unroll
    for (int oi = 0; oi < NMID / 1024; oi++) {
        int o = oi * 1024 + tid;
        float ax = 0.f, ay = 0.f, az = 0.f, aw = 0.f;
#pragma unroll
        for (int g = 0; g < FAN / 8; g++) {
            uint4 iv = g_if4[(size_t)g * NMID + o];
            float4 w0 = wp[(size_t)(2 * g) * NMID + o];
            float4 w1 = wp[(size_t)(2 * g + 1) * NMID + o];
            float4 h0 = hs[iv.x & 0xffff];
            float4 h1 = hs[iv.x >> 16];
            float4 h2 = hs[iv.y & 0xffff];
            float4 h3 = hs[iv.y >> 16];
            float4 h4 = hs[iv.z & 0xffff];
            float4 h5 = hs[iv.z >> 16];
            float4 h6 = hs[iv.w & 0xffff];
            float4 h7 = hs[iv.w >> 16];
            ax = fmaf(w0.x, h0.x, ax); ay = fmaf(w0.x, h0.y, ay);
            az = fmaf(w0.x, h0.z, az); aw = fmaf(w0.x, h0.w, aw);
            ax = fmaf(w0.y, h1.x, ax); ay = fmaf(w0.y, h1.y, ay);
            az = fmaf(w0.y, h1.z, az); aw = fmaf(w0.y, h1.w, aw);
            ax = fmaf(w0.z, h2.x, ax); ay = fmaf(w0.z, h2.y, ay);
            az = fmaf(w0.z, h2.z, az); aw = fmaf(w0.z, h2.w, aw);
            ax = fmaf(w0.w, h3.x, ax); ay = fmaf(w0.w, h3.y, ay);
            az = fmaf(w0.w, h3.z, az); aw = fmaf(w0.w, h3.w, aw);
            ax = fmaf(w1.x, h4.x, ax); ay = fmaf(w1.x, h4.y, ay);
            az = fmaf(w1.x, h4.z, az); aw = fmaf(w1.x, h4.w, aw);
            ax = fmaf(w1.y, h5.x, ax); ay = fmaf(w1.y, h5.y, ay);
            az = fmaf(w1.y, h5.z, az); aw = fmaf(w1.y, h5.w, aw);
            ax = fmaf(w1.z, h6.x, ax); ay = fmaf(w1.z, h6.y, ay);
            az = fmaf(w1.z, h6.z, az); aw = fmaf(w1.z, h6.w, aw);
            ax = fmaf(w1.w, h7.x, ax); ay = fmaf(w1.w, h7.y, ay);
            az = fmaf(w1.w, h7.z, az); aw = fmaf(w1.w, h7.w, aw);
        }
        float bv = bias[o];
        float4 r;
        r.x = fmaxf(ax + bv, 0.f); r.y = fmaxf(ay + bv, 0.f);
        r.z = fmaxf(az + bv, 0.f); r.w = fmaxf(aw + bv, 0.f);
        if (phase == 0) {
            g_act1v[(size_t)o * (B_SZ / 4) + bq] = r;
        } else {
            float vv[4] = {r.x, r.y, r.z, r.w};
#pragma unroll
            for (int i = 0; i < 4; i++) {
                __nv_bfloat16 h, l;
                split_bf16(vv[i], h, l);
                __nv_bfloat16* base = g_a13 + (size_t)(b0 + i) * K3;
                base[o] = h;
                base[NMID + o] = h;
                base[2 * NMID + o] = l;
            }
        }
    }
}

// ---------------------------------------------------------------------------
__global__ void init_out_kernel(const float* __restrict__ bout, float* __restrict__ out) {
    int t = blockIdx.x * blockDim.x + threadIdx.x;
    if (t < B_SZ * NOUT) out[t] = bout[t % NOUT];
}

// ---------------------------------------------------------------------------
extern "C" void kernel_launch(void* const* d_in, const int* in_sizes, int n_in,
                              void* d_out, int out_size) {
    const float* x    = (const float*)d_in[0];
    const float* Win  = (const float*)d_in[1];
    const float* bin  = (const float*)d_in[2];
    const float* Wmid = (const float*)d_in[3];
    const float* bmid = (const float*)d_in[4];
    const float* Wout = (const float*)d_in[5];
    const float* bout = (const float*)d_in[6];
    const int*   idx  = (const int*)d_in[7];    // int32 (JAX x64 disabled)
    float* out = (float*)d_out;

    cudaFuncSetAttribute(cond_kernel, cudaFuncAttributeMaxDynamicSharedMemorySize, 131072);

    // conversions + cond prep (scratch globals bound inside device code)
    cvt3_kernel<0><<<((size_t)NMID * NIN / 4 + 255) / 256, 256>>>(Win);
    cvt3_kernel<1><<<((size_t)B_SZ * NIN / 4 + 255) / 256, 256>>>(x);
    cvt3_kernel<2><<<((size_t)MPAD * NMID / 4 + 255) / 256, 256>>>(Wout);
    prep_w_kernel<<<(NCOND * (FAN / 4) * NMID + 255) / 256, 256>>>(Wmid);
    prep_i_kernel<<<((FAN / 8) * NMID + 255) / 256, 256>>>(idx);

    // GEMM1: relu(W_in x^T + b_in) -> g_act0 fp32 [o][b]
    mma_gemm<0><<<dim3(B_SZ / TBN, NMID / TBM, 1), GEMM_THREADS>>>(bin, nullptr, K1 / TBK);

    // condensed layers
    cond_kernel<<<B_SZ / 4, 1024, 131072>>>(0, bmid);
    cond_kernel<<<B_SZ / 4, 1024, 131072>>>(1, bmid + NMID);

    // GEMM3: out[b][m] = act1 . W_out^T + b_out  (split-K=8, atomic)
    init_out_kernel<<<(B_SZ * NOUT + 255) / 256, 256>>>(bout, out);
    mma_gemm<1><<<dim3(B_SZ / TBN, MPAD / TBM, 8), GEMM_THREADS>>>(nullptr, out, K3 / (TBK * 8));
}